// round 4
// baseline (speedup 1.0000x reference)
#include <cuda_runtime.h>

typedef unsigned long long u64;

#define S_ 512
#define B_ 64
#define H_ 1024
#define G_ 4096   // 4*H
#define NCTA_ 128

// Scratch (allocation-free rule: __device__ globals)
__device__ float g_gi[(size_t)S_ * (size_t)B_ * (size_t)G_];   // 512 MB
__device__ float g_y0[(size_t)S_ * (size_t)B_ * (size_t)H_];   // 128 MB, layer-0 y, [t][b][h]
__device__ float g_ht[2 * (size_t)B_ * (size_t)H_];            // layer-1 h ping-pong [b][h]
__device__ unsigned g_barCnt = 0;
__device__ unsigned g_barGen = 0;

// ---- packed fp32x2 helpers ----
__device__ __forceinline__ u64 pack_dup(float x) {
    u64 r; asm("mov.b64 %0, {%1, %1};" : "=l"(r) : "f"(x)); return r;
}
__device__ __forceinline__ void fma2(u64 &d, u64 a, u64 b) {
    asm("fma.rn.f32x2 %0, %1, %2, %0;" : "+l"(d) : "l"(a), "l"(b));
}
__device__ __forceinline__ float2 unpack2(u64 v) {
    float2 f; asm("mov.b64 {%0, %1}, %2;" : "=f"(f.x), "=f"(f.y) : "l"(v)); return f;
}
__device__ __forceinline__ float sigf(float x) { return 1.0f / (1.0f + __expf(-x)); }
__device__ __forceinline__ float tanhf_(float x) { return 2.0f / (1.0f + __expf(-2.0f * x)) - 1.0f; }

__device__ __forceinline__ void cpasync16(float* dst_smem, const float* src) {
    unsigned d = (unsigned)__cvta_generic_to_shared(dst_smem);
    asm volatile("cp.async.cg.shared.global [%0], [%1], 16;" :: "r"(d), "l"(src));
}

// Device-wide barrier (sense-reversing, NCTA_ resident CTAs).
// Every thread fences so all STG h-writes are release-published before the flag.
__device__ __forceinline__ void gsync() {
    __threadfence();
    __syncthreads();
    if (threadIdx.x == 0) {
        unsigned my = *(volatile unsigned*)&g_barGen;
        if (atomicAdd(&g_barCnt, 1) == NCTA_ - 1) {
            atomicExch(&g_barCnt, 0);
            __threadfence();
            atomicExch(&g_barGen, my + 1);
        } else {
            while (*(volatile unsigned*)&g_barGen == my) __nanosleep(32);
        }
        __threadfence();
    }
    __syncthreads();
}

// ============================================================================
// Input projection GEMM: GI[m,n] = dot(A[m,:], W[n,:]) + bih[n] + bhh[n]
// M=32768 (S*B), N=4096, K=1024. A is [m][k] row-major for BOTH layers
// (layer 1 reads g_y0 which is now stored [t][b][h]).
// Double-buffered smem (1 sync per k-tile) + register prefetch.
// ============================================================================
__global__ __launch_bounds__(256, 2) void gemm_gi(
    int layer, const float* __restrict__ Xin,
    const float* __restrict__ W,
    const float* __restrict__ bih, const float* __restrict__ bhh)
{
    __shared__ __align__(16) float As[2][16][128];
    __shared__ __align__(16) float Bs[2][16][128];
    const float* A = layer ? g_y0 : Xin;
    float* GI = g_gi;
    const int K = H_;
    int bn = blockIdx.x, bm = blockIdx.y;
    int t = threadIdx.x;
    int tx = t & 15, ty = t >> 4;
    int lr = t >> 1;            // tile row (0..127)
    int lc = (t & 1) * 8;       // k-offset within 16-wide tile

    const float* Ap = A + (size_t)(bm * 128 + lr) * K + lc;
    const float* Bp = W + (size_t)(bn * 128 + lr) * K + lc;

    u64 acc[8][4];
#pragma unroll
    for (int i = 0; i < 8; i++)
#pragma unroll
        for (int j = 0; j < 4; j++) acc[i][j] = 0ull;

    float4 ra0, ra1, rb0, rb1;
    ra0 = *(const float4*)(Ap + 0);
    ra1 = *(const float4*)(Ap + 4);
    rb0 = *(const float4*)(Bp + 0);
    rb1 = *(const float4*)(Bp + 4);

    // store tile 0 into buffer 0
    As[0][lc + 0][lr] = ra0.x; As[0][lc + 1][lr] = ra0.y; As[0][lc + 2][lr] = ra0.z; As[0][lc + 3][lr] = ra0.w;
    As[0][lc + 4][lr] = ra1.x; As[0][lc + 5][lr] = ra1.y; As[0][lc + 6][lr] = ra1.z; As[0][lc + 7][lr] = ra1.w;
    Bs[0][lc + 0][lr] = rb0.x; Bs[0][lc + 1][lr] = rb0.y; Bs[0][lc + 2][lr] = rb0.z; Bs[0][lc + 3][lr] = rb0.w;
    Bs[0][lc + 4][lr] = rb1.x; Bs[0][lc + 5][lr] = rb1.y; Bs[0][lc + 6][lr] = rb1.z; Bs[0][lc + 7][lr] = rb1.w;
    __syncthreads();

    for (int kt = 0; kt < K / 16; kt++) {
        int cur = kt & 1;
        if (kt + 1 < K / 16) {
            int k0 = (kt + 1) * 16;
            ra0 = *(const float4*)(Ap + k0);
            ra1 = *(const float4*)(Ap + k0 + 4);
            rb0 = *(const float4*)(Bp + k0);
            rb1 = *(const float4*)(Bp + k0 + 4);
        }
#pragma unroll
        for (int k = 0; k < 16; k++) {
            float4 av0 = *(const float4*)&As[cur][k][ty * 8];
            float4 av1 = *(const float4*)&As[cur][k][ty * 8 + 4];
            const ulonglong2* bp2 = (const ulonglong2*)&Bs[cur][k][tx * 8];
            ulonglong2 bA = bp2[0], bB = bp2[1];
            float a_[8] = {av0.x, av0.y, av0.z, av0.w, av1.x, av1.y, av1.z, av1.w};
#pragma unroll
            for (int i = 0; i < 8; i++) {
                u64 ad = pack_dup(a_[i]);
                fma2(acc[i][0], ad, bA.x);
                fma2(acc[i][1], ad, bA.y);
                fma2(acc[i][2], ad, bB.x);
                fma2(acc[i][3], ad, bB.y);
            }
        }
        if (kt + 1 < K / 16) {
            int nxt = cur ^ 1;
            As[nxt][lc + 0][lr] = ra0.x; As[nxt][lc + 1][lr] = ra0.y; As[nxt][lc + 2][lr] = ra0.z; As[nxt][lc + 3][lr] = ra0.w;
            As[nxt][lc + 4][lr] = ra1.x; As[nxt][lc + 5][lr] = ra1.y; As[nxt][lc + 6][lr] = ra1.z; As[nxt][lc + 7][lr] = ra1.w;
            Bs[nxt][lc + 0][lr] = rb0.x; Bs[nxt][lc + 1][lr] = rb0.y; Bs[nxt][lc + 2][lr] = rb0.z; Bs[nxt][lc + 3][lr] = rb0.w;
            Bs[nxt][lc + 4][lr] = rb1.x; Bs[nxt][lc + 5][lr] = rb1.y; Bs[nxt][lc + 6][lr] = rb1.z; Bs[nxt][lc + 7][lr] = rb1.w;
            __syncthreads();
        }
    }

    int row0 = bm * 128 + ty * 8, col0 = bn * 128 + tx * 8;
#pragma unroll
    for (int i = 0; i < 8; i++) {
#pragma unroll
        for (int jp = 0; jp < 4; jp++) {
            float2 v = unpack2(acc[i][jp]);
            int n0 = col0 + jp * 2;
            GI[(size_t)(row0 + i) * G_ + n0]     = v.x + bih[n0]     + bhh[n0];
            GI[(size_t)(row0 + i) * G_ + n0 + 1] = v.y + bih[n0 + 1] + bhh[n0 + 1];
        }
    }
}

// ============================================================================
// Persistent recurrent layer: 128 CTAs x 512 threads (16 warps).
// CTA owns hidden indices [jb, jb+8) x 4 gates = 32 gate cols x 64 batch.
// Warp wy owns batches [4wy, 4wy+4): streams its own 4 h-rows ([b][k] layout)
// via per-warp cp.async 2-stage pipeline — NO CTA-level sync inside the k loop.
// FFMA2 pairs along k (no per-k dup); W_hh slice resident in smem.
// Gate exchange + cell update are warp-local; c-state lives in 1 reg/thread.
// ============================================================================
#define WSM_F   (32 * 1028)            // [col][k] padded stride 1028
#define HBUF_F  (16 * 2 * 512)         // 16 warps x 2 stages x (4 rows x 128 k)
#define GW_F    (16 * 132)             // 16 warps x [4][33]
#define SMEM_STEP ((WSM_F + HBUF_F + GW_F) * 4)

__global__ __launch_bounds__(512) void lstm_layer(
    int layer, const float* __restrict__ whh,
    float* __restrict__ y1, float* __restrict__ hn_base, float* __restrict__ cn_base)
{
    extern __shared__ float sm[];
    float* Wsm  = sm;                       // [32][1028]
    float* Hbuf = sm + WSM_F;               // per-warp: 2 x [4][128]
    float* Gw   = sm + WSM_F + HBUF_F;      // per-warp: [4][33]

    const size_t BH = (size_t)B_ * H_;
    int tid  = threadIdx.x;
    int lane = tid & 31;                    // gate column within CTA
    int wy   = tid >> 5;                    // warp -> 4-batch group
    int jb   = blockIdx.x * 8;
    int n    = ((lane >> 3) * H_) + jb + (lane & 7);   // global gate column
    int b0   = wy * 4;

    // ---- load W_hh slice into smem once: Wsm[col][k], stride 1028 ----
    {
        int c = tid >> 4, l16 = tid & 15;
        int wn = ((c >> 3) * H_) + jb + (c & 7);
        const float* wrow = whh + (size_t)wn * H_;
#pragma unroll
        for (int q = 0; q < 16; q++) {
            int k = (q * 16 + l16) * 4;
            *(float4*)&Wsm[c * 1028 + k] = *(const float4*)(wrow + k);
        }
    }
    __syncthreads();

    float* hwbuf = Hbuf + wy * 1024;        // 2 stages x 512 floats
    float* gw    = Gw + wy * 132;

    int bl = lane >> 3, j = lane & 7;       // cell mapping (warp-local)
    float cst = 0.0f;                        // persistent cell state

    for (int t = 0; t < S_; t++) {
        const float* gi_t = g_gi + (size_t)t * B_ * G_;
        float gir[4];
#pragma unroll
        for (int r = 0; r < 4; r++)
            gir[r] = gi_t[(size_t)(b0 + r) * G_ + n];

        u64 accA[4] = {0ull, 0ull, 0ull, 0ull};
        u64 accB[4] = {0ull, 0ull, 0ull, 0ull};

        if (t > 0) {
            const float* hsrc = (layer == 0)
                ? (g_y0 + (size_t)(t - 1) * BH)
                : (g_ht + (size_t)((t - 1) & 1) * BH);
            // prologue: chunk 0 -> stage 0 (per-warp, per-lane 16B)
#pragma unroll
            for (int r = 0; r < 4; r++)
                cpasync16(hwbuf + r * 128 + lane * 4,
                          hsrc + (size_t)(b0 + r) * H_ + lane * 4);
            asm volatile("cp.async.commit_group;");

            for (int kc = 0; kc < 8; kc++) {
                if (kc < 7) {
                    float* dst = hwbuf + ((kc + 1) & 1) * 512;
                    const float* src = hsrc + (kc + 1) * 128;
#pragma unroll
                    for (int r = 0; r < 4; r++)
                        cpasync16(dst + r * 128 + lane * 4,
                                  src + (size_t)(b0 + r) * H_ + lane * 4);
                    asm volatile("cp.async.commit_group;");
                    asm volatile("cp.async.wait_group 1;");
                } else {
                    asm volatile("cp.async.wait_group 0;");
                }
                __syncwarp();

                const float* hb = hwbuf + (kc & 1) * 512;
                const float* wp = Wsm + lane * 1028 + kc * 128;
#pragma unroll 4
                for (int k4 = 0; k4 < 32; k4++) {
                    ulonglong2 w2 = *(const ulonglong2*)(wp + k4 * 4);
#pragma unroll
                    for (int r = 0; r < 4; r++) {
                        ulonglong2 h2 = *(const ulonglong2*)(hb + r * 128 + k4 * 4);
                        fma2(accA[r], w2.x, h2.x);
                        fma2(accB[r], w2.y, h2.y);
                    }
                }
                __syncwarp();   // protect stage about to be overwritten
            }
        }

        // gates: horizontal sum + input projection, exchange within warp
#pragma unroll
        for (int r = 0; r < 4; r++) {
            float2 a = unpack2(accA[r]);
            float2 b2 = unpack2(accB[r]);
            gw[r * 33 + lane] = (a.x + a.y) + (b2.x + b2.y) + gir[r];
        }
        __syncwarp();

        float zi = gw[bl * 33 + j];
        float zf = gw[bl * 33 + 8 + j];
        float zg = gw[bl * 33 + 16 + j];
        float zo = gw[bl * 33 + 24 + j];
        cst = sigf(zf) * cst + sigf(zi) * tanhf_(zg);
        float hv = sigf(zo) * tanhf_(cst);

        int bg = b0 + bl;
        float* hdst = (layer == 0) ? (g_y0 + (size_t)t * BH)
                                   : (g_ht + (size_t)(t & 1) * BH);
        hdst[(size_t)bg * H_ + jb + j] = hv;
        if (layer == 1)
            y1[(size_t)t * BH + (size_t)bg * H_ + jb + j] = hv;
        if (t == S_ - 1) {
            size_t o = (size_t)layer * BH + (size_t)bg * H_ + jb + j;
            hn_base[o] = hv;
            cn_base[o] = cst;
        }
        gsync();
    }
}

// ============================================================================
// kernel_launch: 4 graph nodes total.
// Output layout: y1 [S,B,H] | h_n [2,B,H] | c_n [2,B,H]
// ============================================================================
extern "C" void kernel_launch(void* const* d_in, const int* in_sizes, int n_in,
                              void* d_out, int out_size)
{
    const float* x     = (const float*)d_in[0];
    const float* w_ih0 = (const float*)d_in[1];
    const float* w_hh0 = (const float*)d_in[2];
    const float* b_ih0 = (const float*)d_in[3];
    const float* b_hh0 = (const float*)d_in[4];
    const float* w_ih1 = (const float*)d_in[5];
    const float* w_hh1 = (const float*)d_in[6];
    const float* b_ih1 = (const float*)d_in[7];
    const float* b_hh1 = (const float*)d_in[8];

    float* y1 = (float*)d_out;
    float* hn = y1 + (size_t)S_ * B_ * H_;
    float* cn = hn + 2 * (size_t)B_ * H_;

    cudaFuncSetAttribute(lstm_layer, cudaFuncAttributeMaxDynamicSharedMemorySize, SMEM_STEP);

    dim3 ggrid(G_ / 128, (S_ * B_) / 128);  // (32, 256)

    gemm_gi<<<ggrid, 256>>>(0, x, w_ih0, b_ih0, b_hh0);
    lstm_layer<<<NCTA_, 512, SMEM_STEP>>>(0, w_hh0, y1, hn, cn);
    gemm_gi<<<ggrid, 256>>>(1, x, w_ih1, b_ih1, b_hh1);
    lstm_layer<<<NCTA_, 512, SMEM_STEP>>>(1, w_hh1, y1, hn, cn);
}

// round 5
// speedup vs baseline: 1.0199x; 1.0199x over previous
#include <cuda_runtime.h>

typedef unsigned long long u64;

#define S_ 512
#define B_ 64
#define H_ 1024
#define G_ 4096   // 4*H
#define NCTA_ 128

// Scratch (allocation-free rule: __device__ globals)
__device__ float g_gi[(size_t)S_ * (size_t)B_ * (size_t)G_];   // 512 MB
__device__ float g_y0[(size_t)S_ * (size_t)B_ * (size_t)H_];   // 128 MB, layer-0 y, [t][b][h]
__device__ float g_ht[2 * (size_t)B_ * (size_t)H_];            // layer-1 h ping-pong [b][h]
__device__ unsigned g_barCnt = 0;
__device__ unsigned g_barGen = 0;

// ---- packed fp32x2 helpers ----
__device__ __forceinline__ u64 pack_dup(float x) {
    u64 r; asm("mov.b64 %0, {%1, %1};" : "=l"(r) : "f"(x)); return r;
}
__device__ __forceinline__ void fma2(u64 &d, u64 a, u64 b) {
    asm("fma.rn.f32x2 %0, %1, %2, %0;" : "+l"(d) : "l"(a), "l"(b));
}
__device__ __forceinline__ float2 unpack2(u64 v) {
    float2 f; asm("mov.b64 {%0, %1}, %2;" : "=f"(f.x), "=f"(f.y) : "l"(v)); return f;
}
__device__ __forceinline__ float sigf(float x) { return 1.0f / (1.0f + __expf(-x)); }
__device__ __forceinline__ float tanhf_(float x) { return 2.0f / (1.0f + __expf(-2.0f * x)) - 1.0f; }

__device__ __forceinline__ void cpasync16(float* dst_smem, const float* src) {
    unsigned d = (unsigned)__cvta_generic_to_shared(dst_smem);
    asm volatile("cp.async.cg.shared.global [%0], [%1], 16;" :: "r"(d), "l"(src));
}

// Device-wide barrier (sense-reversing, NCTA_ resident CTAs)
__device__ __forceinline__ void gsync() {
    __threadfence();
    __syncthreads();
    if (threadIdx.x == 0) {
        unsigned my = *(volatile unsigned*)&g_barGen;
        if (atomicAdd(&g_barCnt, 1) == NCTA_ - 1) {
            atomicExch(&g_barCnt, 0);
            __threadfence();
            atomicExch(&g_barGen, my + 1);
        } else {
            while (*(volatile unsigned*)&g_barGen == my) __nanosleep(32);
        }
        __threadfence();
    }
    __syncthreads();
}

// ============================================================================
// Input projection GEMM: GI[m,n] = dot(A[m,:], W[n,:]) + bih[n] + bhh[n]
// M=32768 (S*B), N=4096, K=1024. Double-buffered smem + register prefetch.
// ============================================================================
__global__ __launch_bounds__(256, 2) void gemm_gi(
    int layer, const float* __restrict__ Xin,
    const float* __restrict__ W,
    const float* __restrict__ bih, const float* __restrict__ bhh)
{
    __shared__ __align__(16) float As[2][16][128];
    __shared__ __align__(16) float Bs[2][16][128];
    const float* A = layer ? g_y0 : Xin;
    float* GI = g_gi;
    const int K = H_;
    int bn = blockIdx.x, bm = blockIdx.y;
    int t = threadIdx.x;
    int tx = t & 15, ty = t >> 4;
    int lr = t >> 1;
    int lc = (t & 1) * 8;

    const float* Ap = A + (size_t)(bm * 128 + lr) * K + lc;
    const float* Bp = W + (size_t)(bn * 128 + lr) * K + lc;

    u64 acc[8][4];
#pragma unroll
    for (int i = 0; i < 8; i++)
#pragma unroll
        for (int j = 0; j < 4; j++) acc[i][j] = 0ull;

    float4 ra0, ra1, rb0, rb1;
    ra0 = *(const float4*)(Ap + 0);
    ra1 = *(const float4*)(Ap + 4);
    rb0 = *(const float4*)(Bp + 0);
    rb1 = *(const float4*)(Bp + 4);

    As[0][lc + 0][lr] = ra0.x; As[0][lc + 1][lr] = ra0.y; As[0][lc + 2][lr] = ra0.z; As[0][lc + 3][lr] = ra0.w;
    As[0][lc + 4][lr] = ra1.x; As[0][lc + 5][lr] = ra1.y; As[0][lc + 6][lr] = ra1.z; As[0][lc + 7][lr] = ra1.w;
    Bs[0][lc + 0][lr] = rb0.x; Bs[0][lc + 1][lr] = rb0.y; Bs[0][lc + 2][lr] = rb0.z; Bs[0][lc + 3][lr] = rb0.w;
    Bs[0][lc + 4][lr] = rb1.x; Bs[0][lc + 5][lr] = rb1.y; Bs[0][lc + 6][lr] = rb1.z; Bs[0][lc + 7][lr] = rb1.w;
    __syncthreads();

    for (int kt = 0; kt < K / 16; kt++) {
        int cur = kt & 1;
        if (kt + 1 < K / 16) {
            int k0 = (kt + 1) * 16;
            ra0 = *(const float4*)(Ap + k0);
            ra1 = *(const float4*)(Ap + k0 + 4);
            rb0 = *(const float4*)(Bp + k0);
            rb1 = *(const float4*)(Bp + k0 + 4);
        }
#pragma unroll
        for (int k = 0; k < 16; k++) {
            float4 av0 = *(const float4*)&As[cur][k][ty * 8];
            float4 av1 = *(const float4*)&As[cur][k][ty * 8 + 4];
            const ulonglong2* bp2 = (const ulonglong2*)&Bs[cur][k][tx * 8];
            ulonglong2 bA = bp2[0], bB = bp2[1];
            float a_[8] = {av0.x, av0.y, av0.z, av0.w, av1.x, av1.y, av1.z, av1.w};
#pragma unroll
            for (int i = 0; i < 8; i++) {
                u64 ad = pack_dup(a_[i]);
                fma2(acc[i][0], ad, bA.x);
                fma2(acc[i][1], ad, bA.y);
                fma2(acc[i][2], ad, bB.x);
                fma2(acc[i][3], ad, bB.y);
            }
        }
        if (kt + 1 < K / 16) {
            int nxt = cur ^ 1;
            As[nxt][lc + 0][lr] = ra0.x; As[nxt][lc + 1][lr] = ra0.y; As[nxt][lc + 2][lr] = ra0.z; As[nxt][lc + 3][lr] = ra0.w;
            As[nxt][lc + 4][lr] = ra1.x; As[nxt][lc + 5][lr] = ra1.y; As[nxt][lc + 6][lr] = ra1.z; As[nxt][lc + 7][lr] = ra1.w;
            Bs[nxt][lc + 0][lr] = rb0.x; Bs[nxt][lc + 1][lr] = rb0.y; Bs[nxt][lc + 2][lr] = rb0.z; Bs[nxt][lc + 3][lr] = rb0.w;
            Bs[nxt][lc + 4][lr] = rb1.x; Bs[nxt][lc + 5][lr] = rb1.y; Bs[nxt][lc + 6][lr] = rb1.z; Bs[nxt][lc + 7][lr] = rb1.w;
            __syncthreads();
        }
    }

    int row0 = bm * 128 + ty * 8, col0 = bn * 128 + tx * 8;
#pragma unroll
    for (int i = 0; i < 8; i++) {
#pragma unroll
        for (int jp = 0; jp < 4; jp++) {
            float2 v = unpack2(acc[i][jp]);
            int n0 = col0 + jp * 2;
            GI[(size_t)(row0 + i) * G_ + n0]     = v.x + bih[n0]     + bhh[n0];
            GI[(size_t)(row0 + i) * G_ + n0 + 1] = v.y + bih[n0 + 1] + bhh[n0 + 1];
        }
    }
}

// ============================================================================
// Persistent recurrent layer: 128 CTAs x 512 threads (16 warps).
// CTA owns 8 hidden x 4 gates = 32 gate cols x 64 batches x 1024 k.
// Warp wy: kh = wy&1 -> k-half [kh*512, kh*512+512); bg = wy>>1 -> batches
// [bg*8, bg*8+8). Lane = gate column (32).
// W_hh stored in smem as CONFLICT-FREE chunks: Wsm[(k4*32 + col)*4 + j]
// (consecutive lanes read consecutive float4 -> no bank conflicts).
// h streamed per-warp via cp.async 2-stage (64-k chunks), broadcast LDS reads.
// k-halves combined once per step via smem; cell update in kh=0 warps;
// c-state in registers.
// ============================================================================
#define WSM_F   (256 * 32 * 4)         // 32768 floats, [k4][col][4]
#define HBUF_F  (16 * 2 * 8 * 64)      // 16 warps x 2 stages x 8 rows x 64 k
#define CMB_F   (64 * 33)              // [bg*8+r][33]
#define SMEM_STEP ((WSM_F + HBUF_F + CMB_F) * 4)

__global__ __launch_bounds__(512) void lstm_layer(
    int layer, const float* __restrict__ whh,
    float* __restrict__ y1, float* __restrict__ hn_base, float* __restrict__ cn_base)
{
    extern __shared__ float sm[];
    float* Wsm  = sm;                       // [256][32][4]
    float* Hbuf = sm + WSM_F;               // per-warp: 2 x [8][64]
    float* Cmb  = sm + WSM_F + HBUF_F;      // [64][33]

    const size_t BH = (size_t)B_ * H_;
    int tid  = threadIdx.x;
    int lane = tid & 31;                    // gate column within CTA
    int wy   = tid >> 5;
    int kh   = wy & 1;                      // k-half
    int bg   = wy >> 1;                     // batch group (8 batches)
    int jb   = blockIdx.x * 8;
    int n    = ((lane >> 3) * H_) + jb + (lane & 7);   // global gate column
    int b0   = bg * 8;

    // ---- load W_hh slice into conflict-free chunked smem layout ----
    {
        int c = tid & 31;
        int wn = ((c >> 3) * H_) + jb + (c & 7);
        const float* wrow = whh + (size_t)wn * H_;
        int k4b = tid >> 5;                 // 0..15
#pragma unroll
        for (int q = 0; q < 16; q++) {
            int k4 = k4b + q * 16;          // 0..255
            float4 v = *(const float4*)(wrow + k4 * 4);
            *(float4*)&Wsm[((size_t)k4 * 32 + c) * 4] = v;
        }
    }
    __syncthreads();

    float* hwbuf = Hbuf + wy * 1024;        // 2 stages x 512 floats

    float cs0 = 0.0f, cs1 = 0.0f;           // persistent cell state (kh==0 warps)

    for (int t = 0; t < S_; t++) {
        const float* gi_t = g_gi + (size_t)t * B_ * G_;
        float gir[8];
        if (kh == 0) {
#pragma unroll
            for (int r = 0; r < 8; r++)
                gir[r] = gi_t[(size_t)(b0 + r) * G_ + n];
        }

        u64 accA[8], accB[8];
#pragma unroll
        for (int r = 0; r < 8; r++) { accA[r] = 0ull; accB[r] = 0ull; }

        if (t > 0) {
            const float* hsrc = (layer == 0)
                ? (g_y0 + (size_t)(t - 1) * BH)
                : (g_ht + (size_t)((t - 1) & 1) * BH);
            const float* hk = hsrc + kh * 512;

            // prologue: chunk 0 -> stage 0 (8 rows x 64 floats, 4x16B per lane)
#pragma unroll
            for (int q = 0; q < 4; q++) {
                int li = lane + 32 * q;
                int row = li >> 4, off = (li & 15) * 4;
                cpasync16(hwbuf + row * 64 + off,
                          hk + (size_t)(b0 + row) * H_ + off);
            }
            asm volatile("cp.async.commit_group;");

            for (int ch = 0; ch < 8; ch++) {
                if (ch < 7) {
                    float* dst = hwbuf + ((ch + 1) & 1) * 512;
                    const float* src = hk + (ch + 1) * 64;
#pragma unroll
                    for (int q = 0; q < 4; q++) {
                        int li = lane + 32 * q;
                        int row = li >> 4, off = (li & 15) * 4;
                        cpasync16(dst + row * 64 + off,
                                  src + (size_t)(b0 + row) * H_ + off);
                    }
                    asm volatile("cp.async.commit_group;");
                    asm volatile("cp.async.wait_group 1;");
                } else {
                    asm volatile("cp.async.wait_group 0;");
                }
                __syncwarp();

                const float* hs = hwbuf + (ch & 1) * 512;
                const float* wp = Wsm + ((size_t)(kh * 128 + ch * 16) * 32 + lane) * 4;
#pragma unroll 4
                for (int kk = 0; kk < 16; kk++) {
                    ulonglong2 w2 = *(const ulonglong2*)(wp + (size_t)kk * 128);
#pragma unroll
                    for (int r = 0; r < 8; r++) {
                        ulonglong2 h2 = *(const ulonglong2*)(hs + r * 64 + kk * 4);
                        fma2(accA[r], w2.x, h2.x);
                        fma2(accB[r], w2.y, h2.y);
                    }
                }
                __syncwarp();   // protect stage about to be overwritten
            }
        }

        // kh=1 warps publish their partial sums
        if (kh == 1 && t > 0) {
#pragma unroll
            for (int r = 0; r < 8; r++) {
                float2 a = unpack2(accA[r]);
                float2 b2 = unpack2(accB[r]);
                Cmb[(b0 + r) * 33 + lane] = (a.x + a.y) + (b2.x + b2.y);
            }
        }
        __syncthreads();

        if (kh == 0) {
            // combine halves + input projection -> gates in Cmb (in-place slot)
#pragma unroll
            for (int r = 0; r < 8; r++) {
                float2 a = unpack2(accA[r]);
                float2 b2 = unpack2(accB[r]);
                float own = (a.x + a.y) + (b2.x + b2.y);
                float z = own + gir[r] + ((t > 0) ? Cmb[(b0 + r) * 33 + lane] : 0.0f);
                Cmb[(b0 + r) * 33 + lane] = z;
            }
            __syncwarp();

            // cell update: 64 cells per warp, 2 per lane
            float* hdst = (layer == 0) ? (g_y0 + (size_t)t * BH)
                                       : (g_ht + (size_t)(t & 1) * BH);
#pragma unroll
            for (int it = 0; it < 2; it++) {
                int cell = lane + 32 * it;
                int bl = cell >> 3, j = cell & 7;
                const float* gz = &Cmb[(b0 + bl) * 33];
                float zi = gz[j];
                float zf = gz[8 + j];
                float zg = gz[16 + j];
                float zo = gz[24 + j];
                float cold = it ? cs1 : cs0;
                float cnv = sigf(zf) * cold + sigf(zi) * tanhf_(zg);
                float hv = sigf(zo) * tanhf_(cnv);
                if (it) cs1 = cnv; else cs0 = cnv;

                int b = b0 + bl;
                hdst[(size_t)b * H_ + jb + j] = hv;
                if (layer == 1)
                    y1[(size_t)t * BH + (size_t)b * H_ + jb + j] = hv;
                if (t == S_ - 1) {
                    size_t o = (size_t)layer * BH + (size_t)b * H_ + jb + j;
                    hn_base[o] = hv;
                    cn_base[o] = cnv;
                }
            }
        }
        gsync();
    }
}

// ============================================================================
// kernel_launch: 4 graph nodes total.
// Output layout: y1 [S,B,H] | h_n [2,B,H] | c_n [2,B,H]
// ============================================================================
extern "C" void kernel_launch(void* const* d_in, const int* in_sizes, int n_in,
                              void* d_out, int out_size)
{
    const float* x     = (const float*)d_in[0];
    const float* w_ih0 = (const float*)d_in[1];
    const float* w_hh0 = (const float*)d_in[2];
    const float* b_ih0 = (const float*)d_in[3];
    const float* b_hh0 = (const float*)d_in[4];
    const float* w_ih1 = (const float*)d_in[5];
    const float* w_hh1 = (const float*)d_in[6];
    const float* b_ih1 = (const float*)d_in[7];
    const float* b_hh1 = (const float*)d_in[8];

    float* y1 = (float*)d_out;
    float* hn = y1 + (size_t)S_ * B_ * H_;
    float* cn = hn + 2 * (size_t)B_ * H_;

    cudaFuncSetAttribute(lstm_layer, cudaFuncAttributeMaxDynamicSharedMemorySize, SMEM_STEP);

    dim3 ggrid(G_ / 128, (S_ * B_) / 128);  // (32, 256)

    gemm_gi<<<ggrid, 256>>>(0, x, w_ih0, b_ih0, b_hh0);
    lstm_layer<<<NCTA_, 512, SMEM_STEP>>>(0, w_hh0, y1, hn, cn);
    gemm_gi<<<ggrid, 256>>>(1, x, w_ih1, b_ih1, b_hh1);
    lstm_layer<<<NCTA_, 512, SMEM_STEP>>>(1, w_hh1, y1, hn, cn);
}

// round 6
// speedup vs baseline: 1.3355x; 1.3095x over previous
#include <cuda_runtime.h>

typedef unsigned long long u64;

#define S_ 512
#define B_ 64
#define H_ 1024
#define G_ 4096   // 4*H
#define NCTA_ 128

// Scratch (allocation-free rule: __device__ globals)
__device__ float g_gi[(size_t)S_ * (size_t)B_ * (size_t)G_];   // 512 MB
__device__ float g_y0[(size_t)S_ * (size_t)B_ * (size_t)H_];   // 128 MB, layer-0 y, [t][b][h]
__device__ float g_ht[2 * (size_t)B_ * (size_t)H_];            // layer-1 h ping-pong [b][h]
__device__ unsigned g_barCnt = 0;
__device__ unsigned g_barGen = 0;

// ---- packed fp32x2 helpers ----
__device__ __forceinline__ u64 pack_dup(float x) {
    u64 r; asm("mov.b64 %0, {%1, %1};" : "=l"(r) : "f"(x)); return r;
}
__device__ __forceinline__ void fma2(u64 &d, u64 a, u64 b) {
    asm("fma.rn.f32x2 %0, %1, %2, %0;" : "+l"(d) : "l"(a), "l"(b));
}
__device__ __forceinline__ float2 unpack2(u64 v) {
    float2 f; asm("mov.b64 {%0, %1}, %2;" : "=f"(f.x), "=f"(f.y) : "l"(v)); return f;
}
__device__ __forceinline__ float hsum2(u64 v) {
    float2 f = unpack2(v); return f.x + f.y;
}
__device__ __forceinline__ float sigf(float x) { return 1.0f / (1.0f + __expf(-x)); }
__device__ __forceinline__ float tanhf_(float x) { return 2.0f / (1.0f + __expf(-2.0f * x)) - 1.0f; }

__device__ __forceinline__ void cpasync16(float* dst_smem, const float* src) {
    unsigned d = (unsigned)__cvta_generic_to_shared(dst_smem);
    asm volatile("cp.async.cg.shared.global [%0], [%1], 16;" :: "r"(d), "l"(src));
}

// Device-wide barrier (sense-reversing, NCTA_ resident CTAs).
// bar.sync gives CTA-scope ordering of all threads' stores before thread0's
// gpu-scope fence publishes them (grid.sync pattern).
__device__ __forceinline__ void gsync() {
    __syncthreads();
    if (threadIdx.x == 0) {
        __threadfence();
        unsigned my = *(volatile unsigned*)&g_barGen;
        if (atomicAdd(&g_barCnt, 1) == NCTA_ - 1) {
            atomicExch(&g_barCnt, 0);
            __threadfence();
            atomicExch(&g_barGen, my + 1);
        } else {
            while (*(volatile unsigned*)&g_barGen == my) __nanosleep(32);
        }
        __threadfence();
    }
    __syncthreads();
}

// ============================================================================
// Input projection GEMM: GI[m,n] = dot(A[m,:], W[n,:]) + bih[n] + bhh[n]
// M=32768 (S*B), N=4096, K=1024. Double-buffered smem + register prefetch.
// ============================================================================
__global__ __launch_bounds__(256, 2) void gemm_gi(
    int layer, const float* __restrict__ Xin,
    const float* __restrict__ W,
    const float* __restrict__ bih, const float* __restrict__ bhh)
{
    __shared__ __align__(16) float As[2][16][128];
    __shared__ __align__(16) float Bs[2][16][128];
    const float* A = layer ? g_y0 : Xin;
    float* GI = g_gi;
    const int K = H_;
    int bn = blockIdx.x, bm = blockIdx.y;
    int t = threadIdx.x;
    int tx = t & 15, ty = t >> 4;
    int lr = t >> 1;
    int lc = (t & 1) * 8;

    const float* Ap = A + (size_t)(bm * 128 + lr) * K + lc;
    const float* Bp = W + (size_t)(bn * 128 + lr) * K + lc;

    u64 acc[8][4];
#pragma unroll
    for (int i = 0; i < 8; i++)
#pragma unroll
        for (int j = 0; j < 4; j++) acc[i][j] = 0ull;

    float4 ra0, ra1, rb0, rb1;
    ra0 = *(const float4*)(Ap + 0);
    ra1 = *(const float4*)(Ap + 4);
    rb0 = *(const float4*)(Bp + 0);
    rb1 = *(const float4*)(Bp + 4);

    As[0][lc + 0][lr] = ra0.x; As[0][lc + 1][lr] = ra0.y; As[0][lc + 2][lr] = ra0.z; As[0][lc + 3][lr] = ra0.w;
    As[0][lc + 4][lr] = ra1.x; As[0][lc + 5][lr] = ra1.y; As[0][lc + 6][lr] = ra1.z; As[0][lc + 7][lr] = ra1.w;
    Bs[0][lc + 0][lr] = rb0.x; Bs[0][lc + 1][lr] = rb0.y; Bs[0][lc + 2][lr] = rb0.z; Bs[0][lc + 3][lr] = rb0.w;
    Bs[0][lc + 4][lr] = rb1.x; Bs[0][lc + 5][lr] = rb1.y; Bs[0][lc + 6][lr] = rb1.z; Bs[0][lc + 7][lr] = rb1.w;
    __syncthreads();

    for (int kt = 0; kt < K / 16; kt++) {
        int cur = kt & 1;
        if (kt + 1 < K / 16) {
            int k0 = (kt + 1) * 16;
            ra0 = *(const float4*)(Ap + k0);
            ra1 = *(const float4*)(Ap + k0 + 4);
            rb0 = *(const float4*)(Bp + k0);
            rb1 = *(const float4*)(Bp + k0 + 4);
        }
#pragma unroll
        for (int k = 0; k < 16; k++) {
            float4 av0 = *(const float4*)&As[cur][k][ty * 8];
            float4 av1 = *(const float4*)&As[cur][k][ty * 8 + 4];
            const ulonglong2* bp2 = (const ulonglong2*)&Bs[cur][k][tx * 8];
            ulonglong2 bA = bp2[0], bB = bp2[1];
            float a_[8] = {av0.x, av0.y, av0.z, av0.w, av1.x, av1.y, av1.z, av1.w};
#pragma unroll
            for (int i = 0; i < 8; i++) {
                u64 ad = pack_dup(a_[i]);
                fma2(acc[i][0], ad, bA.x);
                fma2(acc[i][1], ad, bA.y);
                fma2(acc[i][2], ad, bB.x);
                fma2(acc[i][3], ad, bB.y);
            }
        }
        if (kt + 1 < K / 16) {
            int nxt = cur ^ 1;
            As[nxt][lc + 0][lr] = ra0.x; As[nxt][lc + 1][lr] = ra0.y; As[nxt][lc + 2][lr] = ra0.z; As[nxt][lc + 3][lr] = ra0.w;
            As[nxt][lc + 4][lr] = ra1.x; As[nxt][lc + 5][lr] = ra1.y; As[nxt][lc + 6][lr] = ra1.z; As[nxt][lc + 7][lr] = ra1.w;
            Bs[nxt][lc + 0][lr] = rb0.x; Bs[nxt][lc + 1][lr] = rb0.y; Bs[nxt][lc + 2][lr] = rb0.z; Bs[nxt][lc + 3][lr] = rb0.w;
            Bs[nxt][lc + 4][lr] = rb1.x; Bs[nxt][lc + 5][lr] = rb1.y; Bs[nxt][lc + 6][lr] = rb1.z; Bs[nxt][lc + 7][lr] = rb1.w;
            __syncthreads();
        }
    }

    int row0 = bm * 128 + ty * 8, col0 = bn * 128 + tx * 8;
#pragma unroll
    for (int i = 0; i < 8; i++) {
#pragma unroll
        for (int jp = 0; jp < 4; jp++) {
            float2 v = unpack2(acc[i][jp]);
            int n0 = col0 + jp * 2;
            GI[(size_t)(row0 + i) * G_ + n0]     = v.x + bih[n0]     + bhh[n0];
            GI[(size_t)(row0 + i) * G_ + n0 + 1] = v.y + bih[n0 + 1] + bhh[n0 + 1];
        }
    }
}

// ============================================================================
// Persistent recurrent layer: 128 CTAs x 512 threads (16 warps).
// CTA owns 8 hidden x 4 gates = 32 gate cols x 64 batches x 1024 k.
// Warp wy: ks = wy&3 -> k-slice of 256; bgrp = wy>>2 -> 16 batches.
// Lane = (lx = lane&3, ly = lane>>2). THREAD TILE = 4 cols x 4 batches:
//   cols   c  = ly*4 + cc   (cc = 0..3)
//   batches b = wb0 + lx + 4*rr (rr = 0..3)
// Per k-quad: 4 w-LDS.128 (conflict-free, lx-broadcast) + 4 h-LDS.128
// (conflict-free via stride-24 pad, ly-broadcast) -> 32 FFMA2. fma-bound.
// k-slices combined via Cmb smem; every thread owns exactly 1 LSTM cell.
// ============================================================================
#define WSM_F   (256 * 32 * 4)          // 32768 floats: [(k4*32 + cc*8 + ly)*4]
#define HSTG_F  (16 * 24)               // per-warp stage: 16 rows x stride 24
#define HBUF_F  (16 * 2 * HSTG_F)       // 12288 floats
#define CMB_F   (4 * 64 * 36)           // 9216 floats: [ks][b][36]
#define SMEM_STEP ((WSM_F + HBUF_F + CMB_F) * 4)

__global__ __launch_bounds__(512) void lstm_layer(
    int layer, const float* __restrict__ whh,
    float* __restrict__ y1, float* __restrict__ hn_base, float* __restrict__ cn_base)
{
    extern __shared__ float sm[];
    float* Wsm  = sm;
    float* Hbuf = sm + WSM_F;
    float* Cmb  = sm + WSM_F + HBUF_F;

    const size_t BH = (size_t)B_ * H_;
    int tid  = threadIdx.x;
    int lane = tid & 31;
    int wy   = tid >> 5;
    int ks   = wy & 3;                  // k-slice (256 k each)
    int wb0  = (wy >> 2) * 16;          // warp batch base
    int lx   = lane & 3;
    int ly   = lane >> 2;
    int jb   = blockIdx.x * 8;

    // ---- load W_hh slice: layout Wsm[k4*128 + cc*32 + ly*4 + j] ----
    {
        int c = tid & 31;
        int wn = ((c >> 3) * H_) + jb + (c & 7);
        const float* wrow = whh + (size_t)wn * H_;
        int dstbase = (c & 3) * 32 + (c >> 2) * 4;
        int k4b = tid >> 5;
#pragma unroll
        for (int q = 0; q < 16; q++) {
            int k4 = k4b + q * 16;      // 0..255
            float4 v = *(const float4*)(wrow + k4 * 4);
            *(float4*)&Wsm[k4 * 128 + dstbase] = v;
        }
    }
    __syncthreads();

    float* hwbuf = Hbuf + wy * (2 * HSTG_F);
    // gi base column for this thread's col-quad (c = ly*4 .. ly*4+3)
    int n_base = ((ly >> 1) * H_) + jb + ((ly & 1) * 4);

    // cell mapping: one cell per thread
    int cb = tid >> 3, cj = tid & 7;
    float cst = 0.0f;

    for (int t = 0; t < S_; t++) {
        const float* gi_t = g_gi + (size_t)t * B_ * G_;
        float4 gi4[4];
        if (ks == 0) {
#pragma unroll
            for (int rr = 0; rr < 4; rr++)
                gi4[rr] = *(const float4*)(gi_t + (size_t)(wb0 + lx + 4 * rr) * G_ + n_base);
        }

        u64 acc[4][4];
#pragma unroll
        for (int cc = 0; cc < 4; cc++)
#pragma unroll
            for (int rr = 0; rr < 4; rr++) acc[cc][rr] = 0ull;

        if (t > 0) {
            const float* hsrc = (layer == 0)
                ? (g_y0 + (size_t)(t - 1) * BH)
                : (g_ht + (size_t)((t - 1) & 1) * BH);
            const float* hk = hsrc + ks * 256;

            // prologue: chunk 0 -> stage 0 (16 rows x 16 k, 2 x 16B per lane)
#pragma unroll
            for (int q = 0; q < 2; q++) {
                int li = lane + 32 * q;
                int rowb = li & 15, kq = li >> 4;
                cpasync16(hwbuf + rowb * 24 + kq * 4,
                          hk + (size_t)(wb0 + rowb) * H_ + kq * 4);
            }
            asm volatile("cp.async.commit_group;");

            for (int ch = 0; ch < 16; ch++) {
                if (ch < 15) {
                    float* dst = hwbuf + ((ch + 1) & 1) * HSTG_F;
                    const float* src = hk + (ch + 1) * 16;
#pragma unroll
                    for (int q = 0; q < 2; q++) {
                        int li = lane + 32 * q;
                        int rowb = li & 15, kq = li >> 4;
                        cpasync16(dst + rowb * 24 + kq * 4,
                                  src + (size_t)(wb0 + rowb) * H_ + kq * 4);
                    }
                    asm volatile("cp.async.commit_group;");
                    asm volatile("cp.async.wait_group 1;");
                } else {
                    asm volatile("cp.async.wait_group 0;");
                }
                __syncwarp();

                const float* hs = hwbuf + (ch & 1) * HSTG_F;
                int k4g0 = ks * 64 + ch * 4;
#pragma unroll
                for (int k4in = 0; k4in < 4; k4in++) {
                    const float* wp = Wsm + (k4g0 + k4in) * 128 + ly * 4;
                    ulonglong2 w0 = *(const ulonglong2*)(wp + 0);
                    ulonglong2 w1 = *(const ulonglong2*)(wp + 32);
                    ulonglong2 w2 = *(const ulonglong2*)(wp + 64);
                    ulonglong2 w3 = *(const ulonglong2*)(wp + 96);
                    const float* hp = hs + lx * 24 + k4in * 4;
                    ulonglong2 h0 = *(const ulonglong2*)(hp + 0 * 24);
                    ulonglong2 h1 = *(const ulonglong2*)(hp + 4 * 24);
                    ulonglong2 h2 = *(const ulonglong2*)(hp + 8 * 24);
                    ulonglong2 h3 = *(const ulonglong2*)(hp + 12 * 24);

                    fma2(acc[0][0], w0.x, h0.x); fma2(acc[0][0], w0.y, h0.y);
                    fma2(acc[1][0], w1.x, h0.x); fma2(acc[1][0], w1.y, h0.y);
                    fma2(acc[2][0], w2.x, h0.x); fma2(acc[2][0], w2.y, h0.y);
                    fma2(acc[3][0], w3.x, h0.x); fma2(acc[3][0], w3.y, h0.y);
                    fma2(acc[0][1], w0.x, h1.x); fma2(acc[0][1], w0.y, h1.y);
                    fma2(acc[1][1], w1.x, h1.x); fma2(acc[1][1], w1.y, h1.y);
                    fma2(acc[2][1], w2.x, h1.x); fma2(acc[2][1], w2.y, h1.y);
                    fma2(acc[3][1], w3.x, h1.x); fma2(acc[3][1], w3.y, h1.y);
                    fma2(acc[0][2], w0.x, h2.x); fma2(acc[0][2], w0.y, h2.y);
                    fma2(acc[1][2], w1.x, h2.x); fma2(acc[1][2], w1.y, h2.y);
                    fma2(acc[2][2], w2.x, h2.x); fma2(acc[2][2], w2.y, h2.y);
                    fma2(acc[3][2], w3.x, h2.x); fma2(acc[3][2], w3.y, h2.y);
                    fma2(acc[0][3], w0.x, h3.x); fma2(acc[0][3], w0.y, h3.y);
                    fma2(acc[1][3], w1.x, h3.x); fma2(acc[1][3], w1.y, h3.y);
                    fma2(acc[2][3], w2.x, h3.x); fma2(acc[2][3], w2.y, h3.y);
                    fma2(acc[3][3], w3.x, h3.x); fma2(acc[3][3], w3.y, h3.y);
                }
                __syncwarp();   // protect stage about to be overwritten
            }
        }

        // publish partials (k-slice 0 folds gi in first)
#pragma unroll
        for (int rr = 0; rr < 4; rr++) {
            float4 v;
            v.x = hsum2(acc[0][rr]);
            v.y = hsum2(acc[1][rr]);
            v.z = hsum2(acc[2][rr]);
            v.w = hsum2(acc[3][rr]);
            if (ks == 0) {
                v.x += gi4[rr].x; v.y += gi4[rr].y;
                v.z += gi4[rr].z; v.w += gi4[rr].w;
            }
            int b = wb0 + lx + 4 * rr;
            *(float4*)&Cmb[(ks * 64 + b) * 36 + ly * 4] = v;
        }
        __syncthreads();

        // combine k-slices + cell update: one cell per thread
        float z[4];
#pragma unroll
        for (int g = 0; g < 4; g++) {
            int c = g * 8 + cj;
            z[g] = Cmb[(0 * 64 + cb) * 36 + c]
                 + Cmb[(1 * 64 + cb) * 36 + c]
                 + Cmb[(2 * 64 + cb) * 36 + c]
                 + Cmb[(3 * 64 + cb) * 36 + c];
        }
        cst = sigf(z[1]) * cst + sigf(z[0]) * tanhf_(z[2]);
        float hv = sigf(z[3]) * tanhf_(cst);

        float* hdst = (layer == 0) ? (g_y0 + (size_t)t * BH)
                                   : (g_ht + (size_t)(t & 1) * BH);
        hdst[(size_t)cb * H_ + jb + cj] = hv;
        if (layer == 1)
            y1[(size_t)t * BH + (size_t)cb * H_ + jb + cj] = hv;
        if (t == S_ - 1) {
            size_t o = (size_t)layer * BH + (size_t)cb * H_ + jb + cj;
            hn_base[o] = hv;
            cn_base[o] = cst;
        }
        gsync();
    }
}

// ============================================================================
// kernel_launch: 4 graph nodes total.
// Output layout: y1 [S,B,H] | h_n [2,B,H] | c_n [2,B,H]
// ============================================================================
extern "C" void kernel_launch(void* const* d_in, const int* in_sizes, int n_in,
                              void* d_out, int out_size)
{
    const float* x     = (const float*)d_in[0];
    const float* w_ih0 = (const float*)d_in[1];
    const float* w_hh0 = (const float*)d_in[2];
    const float* b_ih0 = (const float*)d_in[3];
    const float* b_hh0 = (const float*)d_in[4];
    const float* w_ih1 = (const float*)d_in[5];
    const float* w_hh1 = (const float*)d_in[6];
    const float* b_ih1 = (const float*)d_in[7];
    const float* b_hh1 = (const float*)d_in[8];

    float* y1 = (float*)d_out;
    float* hn = y1 + (size_t)S_ * B_ * H_;
    float* cn = hn + 2 * (size_t)B_ * H_;

    cudaFuncSetAttribute(lstm_layer, cudaFuncAttributeMaxDynamicSharedMemorySize, SMEM_STEP);

    dim3 ggrid(G_ / 128, (S_ * B_) / 128);  // (32, 256)

    gemm_gi<<<ggrid, 256>>>(0, x, w_ih0, b_ih0, b_hh0);
    lstm_layer<<<NCTA_, 512, SMEM_STEP>>>(0, w_hh0, y1, hn, cn);
    gemm_gi<<<ggrid, 256>>>(1, x, w_ih1, b_ih1, b_hh1);
    lstm_layer<<<NCTA_, 512, SMEM_STEP>>>(1, w_hh1, y1, hn, cn);
}

// round 7
// speedup vs baseline: 1.3567x; 1.0159x over previous
#include <cuda_runtime.h>

typedef unsigned long long u64;

#define S_ 512
#define B_ 64
#define H_ 1024
#define G_ 4096   // 4*H
#define NCTA_ 128

// Scratch (allocation-free rule: __device__ globals)
__device__ float g_gi[(size_t)S_ * (size_t)B_ * (size_t)G_];   // 512 MB
__device__ float g_y0[(size_t)S_ * (size_t)B_ * (size_t)H_];   // 128 MB, layer-0 y, [t][b][h]
__device__ float g_ht[2 * (size_t)B_ * (size_t)H_];            // layer-1 h ping-pong [b][h]
__device__ unsigned g_barCnt = 0;
__device__ unsigned g_barGen = 0;

// ---- packed fp32x2 helpers ----
__device__ __forceinline__ u64 pack_dup(float x) {
    u64 r; asm("mov.b64 %0, {%1, %1};" : "=l"(r) : "f"(x)); return r;
}
__device__ __forceinline__ void fma2(u64 &d, u64 a, u64 b) {
    asm("fma.rn.f32x2 %0, %1, %2, %0;" : "+l"(d) : "l"(a), "l"(b));
}
__device__ __forceinline__ float2 unpack2(u64 v) {
    float2 f; asm("mov.b64 {%0, %1}, %2;" : "=f"(f.x), "=f"(f.y) : "l"(v)); return f;
}
__device__ __forceinline__ float hsum2(u64 v) {
    float2 f = unpack2(v); return f.x + f.y;
}
__device__ __forceinline__ float sigf(float x) { return 1.0f / (1.0f + __expf(-x)); }
__device__ __forceinline__ float tanhf_(float x) { return 2.0f / (1.0f + __expf(-2.0f * x)) - 1.0f; }

__device__ __forceinline__ void cpasync16(float* dst_smem, const float* src) {
    unsigned d = (unsigned)__cvta_generic_to_shared(dst_smem);
    asm volatile("cp.async.cg.shared.global [%0], [%1], 16;" :: "r"(d), "l"(src));
}

// Device-wide barrier (sense-reversing, NCTA_ resident CTAs).
__device__ __forceinline__ void gsync() {
    __syncthreads();
    if (threadIdx.x == 0) {
        __threadfence();
        unsigned my = *(volatile unsigned*)&g_barGen;
        if (atomicAdd(&g_barCnt, 1) == NCTA_ - 1) {
            atomicExch(&g_barCnt, 0);
            __threadfence();
            atomicExch(&g_barGen, my + 1);
        } else {
            while (*(volatile unsigned*)&g_barGen == my) __nanosleep(32);
        }
        __threadfence();
    }
    __syncthreads();
}

// ============================================================================
// Input projection GEMM: GI[m,n] = dot(A[m,:], W[n,:]) + bih[n] + bhh[n]
// M=32768 (S*B), N=4096, K=1024. Double-buffered smem + register prefetch.
// ============================================================================
__global__ __launch_bounds__(256, 2) void gemm_gi(
    int layer, const float* __restrict__ Xin,
    const float* __restrict__ W,
    const float* __restrict__ bih, const float* __restrict__ bhh)
{
    __shared__ __align__(16) float As[2][16][128];
    __shared__ __align__(16) float Bs[2][16][128];
    const float* A = layer ? g_y0 : Xin;
    float* GI = g_gi;
    const int K = H_;
    int bn = blockIdx.x, bm = blockIdx.y;
    int t = threadIdx.x;
    int tx = t & 15, ty = t >> 4;
    int lr = t >> 1;
    int lc = (t & 1) * 8;

    const float* Ap = A + (size_t)(bm * 128 + lr) * K + lc;
    const float* Bp = W + (size_t)(bn * 128 + lr) * K + lc;

    u64 acc[8][4];
#pragma unroll
    for (int i = 0; i < 8; i++)
#pragma unroll
        for (int j = 0; j < 4; j++) acc[i][j] = 0ull;

    float4 ra0, ra1, rb0, rb1;
    ra0 = *(const float4*)(Ap + 0);
    ra1 = *(const float4*)(Ap + 4);
    rb0 = *(const float4*)(Bp + 0);
    rb1 = *(const float4*)(Bp + 4);

    As[0][lc + 0][lr] = ra0.x; As[0][lc + 1][lr] = ra0.y; As[0][lc + 2][lr] = ra0.z; As[0][lc + 3][lr] = ra0.w;
    As[0][lc + 4][lr] = ra1.x; As[0][lc + 5][lr] = ra1.y; As[0][lc + 6][lr] = ra1.z; As[0][lc + 7][lr] = ra1.w;
    Bs[0][lc + 0][lr] = rb0.x; Bs[0][lc + 1][lr] = rb0.y; Bs[0][lc + 2][lr] = rb0.z; Bs[0][lc + 3][lr] = rb0.w;
    Bs[0][lc + 4][lr] = rb1.x; Bs[0][lc + 5][lr] = rb1.y; Bs[0][lc + 6][lr] = rb1.z; Bs[0][lc + 7][lr] = rb1.w;
    __syncthreads();

    for (int kt = 0; kt < K / 16; kt++) {
        int cur = kt & 1;
        if (kt + 1 < K / 16) {
            int k0 = (kt + 1) * 16;
            ra0 = *(const float4*)(Ap + k0);
            ra1 = *(const float4*)(Ap + k0 + 4);
            rb0 = *(const float4*)(Bp + k0);
            rb1 = *(const float4*)(Bp + k0 + 4);
        }
#pragma unroll
        for (int k = 0; k < 16; k++) {
            float4 av0 = *(const float4*)&As[cur][k][ty * 8];
            float4 av1 = *(const float4*)&As[cur][k][ty * 8 + 4];
            const ulonglong2* bp2 = (const ulonglong2*)&Bs[cur][k][tx * 8];
            ulonglong2 bA = bp2[0], bB = bp2[1];
            float a_[8] = {av0.x, av0.y, av0.z, av0.w, av1.x, av1.y, av1.z, av1.w};
#pragma unroll
            for (int i = 0; i < 8; i++) {
                u64 ad = pack_dup(a_[i]);
                fma2(acc[i][0], ad, bA.x);
                fma2(acc[i][1], ad, bA.y);
                fma2(acc[i][2], ad, bB.x);
                fma2(acc[i][3], ad, bB.y);
            }
        }
        if (kt + 1 < K / 16) {
            int nxt = cur ^ 1;
            As[nxt][lc + 0][lr] = ra0.x; As[nxt][lc + 1][lr] = ra0.y; As[nxt][lc + 2][lr] = ra0.z; As[nxt][lc + 3][lr] = ra0.w;
            As[nxt][lc + 4][lr] = ra1.x; As[nxt][lc + 5][lr] = ra1.y; As[nxt][lc + 6][lr] = ra1.z; As[nxt][lc + 7][lr] = ra1.w;
            Bs[nxt][lc + 0][lr] = rb0.x; Bs[nxt][lc + 1][lr] = rb0.y; Bs[nxt][lc + 2][lr] = rb0.z; Bs[nxt][lc + 3][lr] = rb0.w;
            Bs[nxt][lc + 4][lr] = rb1.x; Bs[nxt][lc + 5][lr] = rb1.y; Bs[nxt][lc + 6][lr] = rb1.z; Bs[nxt][lc + 7][lr] = rb1.w;
            __syncthreads();
        }
    }

    int row0 = bm * 128 + ty * 8, col0 = bn * 128 + tx * 8;
#pragma unroll
    for (int i = 0; i < 8; i++) {
#pragma unroll
        for (int jp = 0; jp < 4; jp++) {
            float2 v = unpack2(acc[i][jp]);
            int n0 = col0 + jp * 2;
            GI[(size_t)(row0 + i) * G_ + n0]     = v.x + bih[n0]     + bhh[n0];
            GI[(size_t)(row0 + i) * G_ + n0 + 1] = v.y + bih[n0 + 1] + bhh[n0 + 1];
        }
    }
}

// ============================================================================
// Persistent recurrent layer: 128 CTAs x 512 threads (16 warps).
// Same structure as round 6 (2-D 4x4 register tile, conflict-free smem),
// plus EXPLICIT register double-buffering across k4 iterations so the 8
// LDS.128 of the next k4 overlap the 32 FFMA2 of the current one.
// ============================================================================
#define WSM_F   (256 * 32 * 4)          // 32768 floats: [k4][cc][ly][4]
#define HSTG_F  (16 * 24)               // per-warp stage: 16 rows x stride 24
#define HBUF_F  (16 * 2 * HSTG_F)       // 12288 floats
#define CMB_F   (4 * 64 * 36)           // 9216 floats: [ks][b][36]
#define SMEM_STEP ((WSM_F + HBUF_F + CMB_F) * 4)

struct Ops {
    ulonglong2 w0, w1, w2, w3;
    ulonglong2 h0, h1, h2, h3;
};

__device__ __forceinline__ void load_ops(Ops &o, const float* wp, const float* hp) {
    o.w0 = *(const ulonglong2*)(wp + 0);
    o.w1 = *(const ulonglong2*)(wp + 32);
    o.w2 = *(const ulonglong2*)(wp + 64);
    o.w3 = *(const ulonglong2*)(wp + 96);
    o.h0 = *(const ulonglong2*)(hp + 0 * 24);
    o.h1 = *(const ulonglong2*)(hp + 4 * 24);
    o.h2 = *(const ulonglong2*)(hp + 8 * 24);
    o.h3 = *(const ulonglong2*)(hp + 12 * 24);
}

__device__ __forceinline__ void do_fma(u64 (&acc)[4][4], const Ops &o) {
    fma2(acc[0][0], o.w0.x, o.h0.x); fma2(acc[0][0], o.w0.y, o.h0.y);
    fma2(acc[1][0], o.w1.x, o.h0.x); fma2(acc[1][0], o.w1.y, o.h0.y);
    fma2(acc[2][0], o.w2.x, o.h0.x); fma2(acc[2][0], o.w2.y, o.h0.y);
    fma2(acc[3][0], o.w3.x, o.h0.x); fma2(acc[3][0], o.w3.y, o.h0.y);
    fma2(acc[0][1], o.w0.x, o.h1.x); fma2(acc[0][1], o.w0.y, o.h1.y);
    fma2(acc[1][1], o.w1.x, o.h1.x); fma2(acc[1][1], o.w1.y, o.h1.y);
    fma2(acc[2][1], o.w2.x, o.h1.x); fma2(acc[2][1], o.w2.y, o.h1.y);
    fma2(acc[3][1], o.w3.x, o.h1.x); fma2(acc[3][1], o.w3.y, o.h1.y);
    fma2(acc[0][2], o.w0.x, o.h2.x); fma2(acc[0][2], o.w0.y, o.h2.y);
    fma2(acc[1][2], o.w1.x, o.h2.x); fma2(acc[1][2], o.w1.y, o.h2.y);
    fma2(acc[2][2], o.w2.x, o.h2.x); fma2(acc[2][2], o.w2.y, o.h2.y);
    fma2(acc[3][2], o.w3.x, o.h2.x); fma2(acc[3][2], o.w3.y, o.h2.y);
    fma2(acc[0][3], o.w0.x, o.h3.x); fma2(acc[0][3], o.w0.y, o.h3.y);
    fma2(acc[1][3], o.w1.x, o.h3.x); fma2(acc[1][3], o.w1.y, o.h3.y);
    fma2(acc[2][3], o.w2.x, o.h3.x); fma2(acc[2][3], o.w2.y, o.h3.y);
    fma2(acc[3][3], o.w3.x, o.h3.x); fma2(acc[3][3], o.w3.y, o.h3.y);
}

__global__ __launch_bounds__(512, 1) void lstm_layer(
    int layer, const float* __restrict__ whh,
    float* __restrict__ y1, float* __restrict__ hn_base, float* __restrict__ cn_base)
{
    extern __shared__ float sm[];
    float* Wsm  = sm;
    float* Hbuf = sm + WSM_F;
    float* Cmb  = sm + WSM_F + HBUF_F;

    const size_t BH = (size_t)B_ * H_;
    int tid  = threadIdx.x;
    int lane = tid & 31;
    int wy   = tid >> 5;
    int ks   = wy & 3;                  // k-slice (256 k each)
    int wb0  = (wy >> 2) * 16;          // warp batch base
    int lx   = lane & 3;
    int ly   = lane >> 2;
    int jb   = blockIdx.x * 8;

    // ---- load W_hh slice: layout Wsm[k4*128 + cc*32 + ly*4 + j] ----
    {
        int c = tid & 31;
        int wn = ((c >> 3) * H_) + jb + (c & 7);
        const float* wrow = whh + (size_t)wn * H_;
        int dstbase = (c & 3) * 32 + (c >> 2) * 4;
        int k4b = tid >> 5;
#pragma unroll
        for (int q = 0; q < 16; q++) {
            int k4 = k4b + q * 16;      // 0..255
            float4 v = *(const float4*)(wrow + k4 * 4);
            *(float4*)&Wsm[k4 * 128 + dstbase] = v;
        }
    }
    __syncthreads();

    float* hwbuf = Hbuf + wy * (2 * HSTG_F);
    int n_base = ((ly >> 1) * H_) + jb + ((ly & 1) * 4);

    // cell mapping: one cell per thread
    int cb = tid >> 3, cj = tid & 7;
    float cst = 0.0f;

    for (int t = 0; t < S_; t++) {
        const float* gi_t = g_gi + (size_t)t * B_ * G_;
        float4 gi4[4];
        if (ks == 0) {
#pragma unroll
            for (int rr = 0; rr < 4; rr++)
                gi4[rr] = *(const float4*)(gi_t + (size_t)(wb0 + lx + 4 * rr) * G_ + n_base);
        }

        u64 acc[4][4];
#pragma unroll
        for (int cc = 0; cc < 4; cc++)
#pragma unroll
            for (int rr = 0; rr < 4; rr++) acc[cc][rr] = 0ull;

        if (t > 0) {
            const float* hsrc = (layer == 0)
                ? (g_y0 + (size_t)(t - 1) * BH)
                : (g_ht + (size_t)((t - 1) & 1) * BH);
            const float* hk = hsrc + ks * 256;

            // prologue: chunk 0 -> stage 0
#pragma unroll
            for (int q = 0; q < 2; q++) {
                int li = lane + 32 * q;
                int rowb = li & 15, kq = li >> 4;
                cpasync16(hwbuf + rowb * 24 + kq * 4,
                          hk + (size_t)(wb0 + rowb) * H_ + kq * 4);
            }
            asm volatile("cp.async.commit_group;");

            for (int ch = 0; ch < 16; ch++) {
                if (ch < 15) {
                    float* dst = hwbuf + ((ch + 1) & 1) * HSTG_F;
                    const float* src = hk + (ch + 1) * 16;
#pragma unroll
                    for (int q = 0; q < 2; q++) {
                        int li = lane + 32 * q;
                        int rowb = li & 15, kq = li >> 4;
                        cpasync16(dst + rowb * 24 + kq * 4,
                                  src + (size_t)(wb0 + rowb) * H_ + kq * 4);
                    }
                    asm volatile("cp.async.commit_group;");
                    asm volatile("cp.async.wait_group 1;");
                } else {
                    asm volatile("cp.async.wait_group 0;");
                }
                __syncwarp();

                const float* hs = hwbuf + (ch & 1) * HSTG_F;
                int k4g0 = ks * 64 + ch * 4;
                const float* wbase = Wsm + (size_t)k4g0 * 128 + ly * 4;
                const float* hbase = hs + lx * 24;

                // explicit register double-buffer across the 4 k4 iterations
                Ops ops0, ops1;
                load_ops(ops0, wbase, hbase);
                load_ops(ops1, wbase + 128, hbase + 4);
                do_fma(acc, ops0);
                load_ops(ops0, wbase + 256, hbase + 8);
                do_fma(acc, ops1);
                load_ops(ops1, wbase + 384, hbase + 12);
                do_fma(acc, ops0);
                do_fma(acc, ops1);

                __syncwarp();   // protect stage about to be overwritten
            }
        }

        // publish partials (k-slice 0 folds gi in first)
#pragma unroll
        for (int rr = 0; rr < 4; rr++) {
            float4 v;
            v.x = hsum2(acc[0][rr]);
            v.y = hsum2(acc[1][rr]);
            v.z = hsum2(acc[2][rr]);
            v.w = hsum2(acc[3][rr]);
            if (ks == 0) {
                v.x += gi4[rr].x; v.y += gi4[rr].y;
                v.z += gi4[rr].z; v.w += gi4[rr].w;
            }
            int b = wb0 + lx + 4 * rr;
            *(float4*)&Cmb[(ks * 64 + b) * 36 + ly * 4] = v;
        }
        __syncthreads();

        // combine k-slices + cell update: one cell per thread
        float z[4];
#pragma unroll
        for (int g = 0; g < 4; g++) {
            int c = g * 8 + cj;
            z[g] = Cmb[(0 * 64 + cb) * 36 + c]
                 + Cmb[(1 * 64 + cb) * 36 + c]
                 + Cmb[(2 * 64 + cb) * 36 + c]
                 + Cmb[(3 * 64 + cb) * 36 + c];
        }
        cst = sigf(z[1]) * cst + sigf(z[0]) * tanhf_(z[2]);
        float hv = sigf(z[3]) * tanhf_(cst);

        float* hdst = (layer == 0) ? (g_y0 + (size_t)t * BH)
                                   : (g_ht + (size_t)(t & 1) * BH);
        hdst[(size_t)cb * H_ + jb + cj] = hv;
        if (layer == 1)
            y1[(size_t)t * BH + (size_t)cb * H_ + jb + cj] = hv;
        if (t == S_ - 1) {
            size_t o = (size_t)layer * BH + (size_t)cb * H_ + jb + cj;
            hn_base[o] = hv;
            cn_base[o] = cst;
        }
        gsync();
    }
}

// ============================================================================
// kernel_launch: 4 graph nodes total.
// Output layout: y1 [S,B,H] | h_n [2,B,H] | c_n [2,B,H]
// ============================================================================
extern "C" void kernel_launch(void* const* d_in, const int* in_sizes, int n_in,
                              void* d_out, int out_size)
{
    const float* x     = (const float*)d_in[0];
    const float* w_ih0 = (const float*)d_in[1];
    const float* w_hh0 = (const float*)d_in[2];
    const float* b_ih0 = (const float*)d_in[3];
    const float* b_hh0 = (const float*)d_in[4];
    const float* w_ih1 = (const float*)d_in[5];
    const float* w_hh1 = (const float*)d_in[6];
    const float* b_ih1 = (const float*)d_in[7];
    const float* b_hh1 = (const float*)d_in[8];

    float* y1 = (float*)d_out;
    float* hn = y1 + (size_t)S_ * B_ * H_;
    float* cn = hn + 2 * (size_t)B_ * H_;

    cudaFuncSetAttribute(lstm_layer, cudaFuncAttributeMaxDynamicSharedMemorySize, SMEM_STEP);

    dim3 ggrid(G_ / 128, (S_ * B_) / 128);  // (32, 256)

    gemm_gi<<<ggrid, 256>>>(0, x, w_ih0, b_ih0, b_hh0);
    lstm_layer<<<NCTA_, 512, SMEM_STEP>>>(0, w_hh0, y1, hn, cn);
    gemm_gi<<<ggrid, 256>>>(1, x, w_ih1, b_ih1, b_hh1);
    lstm_layer<<<NCTA_, 512, SMEM_STEP>>>(1, w_hh1, y1, hn, cn);
}